// round 12
// baseline (speedup 1.0000x reference)
#include <cuda_runtime.h>
#include <cuda_fp16.h>
#include <cstdint>

#define NSP 100000
#define NRX 200000
#define NED 1000000
#define DM  128
#define BGR 50
#define NS_PER 2000
#define NR_PER 4000

// State / message buffers — all fp16
__device__ __half g_hsA[NSP * DM];
__device__ __half g_hsB[NSP * DM];
__device__ __half g_hrA[NRX * DM];
__device__ __half g_hrB[NRX * DM];
__device__ __half g_y[NSP * DM];
__device__ __half g_z[NRX * DM];
// Pre-transposed fp16 weights: [which of 4][n=128][k=256]
__device__ __half g_wt[4][128 * 256];

// ---------------------------------------------------------------------------
__device__ __forceinline__ uint32_t smem_u32(const void* p) {
    uint32_t a;
    asm("{ .reg .u64 t; cvta.to.shared.u64 t, %1; cvt.u32.u64 %0, t; }" : "=r"(a) : "l"(p));
    return a;
}
__device__ __forceinline__ void ldsm4(uint32_t r[4], uint32_t addr) {
    asm volatile("ldmatrix.sync.aligned.m8n8.x4.shared.b16 {%0,%1,%2,%3}, [%4];"
                 : "=r"(r[0]), "=r"(r[1]), "=r"(r[2]), "=r"(r[3]) : "r"(addr));
}
__device__ __forceinline__ void mma16816(float c[4], const uint32_t a[4],
                                         uint32_t b0, uint32_t b1) {
    asm volatile(
        "mma.sync.aligned.m16n8k16.row.col.f32.f16.f16.f32 "
        "{%0,%1,%2,%3}, {%4,%5,%6,%7}, {%8,%9}, {%0,%1,%2,%3};"
        : "+f"(c[0]), "+f"(c[1]), "+f"(c[2]), "+f"(c[3])
        : "r"(a[0]), "r"(a[1]), "r"(a[2]), "r"(a[3]), "r"(b0), "r"(b1));
}
__device__ __forceinline__ void cpa16(uint32_t smem, const void* gmem, uint32_t bytes) {
    asm volatile("cp.async.ca.shared.global [%0], [%1], 16, %2;"
                 :: "r"(smem), "l"(gmem), "r"(bytes) : "memory");
}

// ---------------------------------------------------------------------------
// Fused init + weight prep:
//   blocks [0, IBS)            : h_s init
//   blocks [IBS, IBS+IBR)      : h_r init
//   blocks [IBS+IBR, +512)     : W transpose/convert
#define IBS ((NSP * 32 + 255) / 256)
#define IBR ((NRX * 32 + 255) / 256)
__global__ void k_init(const int* __restrict__ sidx, const int* __restrict__ ext,
                       const float* __restrict__ st, const float* __restrict__ et,
                       const int* __restrict__ tids, const float* __restrict__ params,
                       const float* __restrict__ tt, const float* __restrict__ Wp,
                       const float* __restrict__ bp,
                       const float* __restrict__ Wr, const float* __restrict__ Ws,
                       __half* __restrict__ hs, __half* __restrict__ hr) {
    if ((int)blockIdx.x < IBS) {
        int t = blockIdx.x * blockDim.x + threadIdx.x;
        int row = t >> 5, c = t & 31;
        if (row >= NSP) return;
        int si = sidx[row], ei = ext[row];
        float4 a = ((const float4*)st)[si * 32 + c];
        float4 b = ((const float4*)et)[ei * 32 + c];
        __half2 o01 = __floats2half2_rn(a.x + b.x, a.y + b.y);
        __half2 o23 = __floats2half2_rn(a.z + b.z, a.w + b.w);
        uint2 o;
        o.x = *(uint32_t*)&o01; o.y = *(uint32_t*)&o23;
        ((uint2*)hs)[row * 32 + c] = o;
    } else if ((int)blockIdx.x < IBS + IBR) {
        int t = ((int)blockIdx.x - IBS) * blockDim.x + threadIdx.x;
        int row = t >> 5, c = t & 31;
        if (row >= NRX) return;
        int ti = tids[row];
        float4 acc = ((const float4*)tt)[ti * 32 + c];
        float4 bb  = ((const float4*)bp)[c];
        acc.x += bb.x; acc.y += bb.y; acc.z += bb.z; acc.w += bb.w;
#pragma unroll
        for (int k = 0; k < 8; k++) {
            float p = params[row * 8 + k];
            float4 w = ((const float4*)Wp)[k * 32 + c];
            acc.x += p * w.x; acc.y += p * w.y; acc.z += p * w.z; acc.w += p * w.w;
        }
        __half2 o01 = __floats2half2_rn(acc.x, acc.y);
        __half2 o23 = __floats2half2_rn(acc.z, acc.w);
        uint2 o;
        o.x = *(uint32_t*)&o01; o.y = *(uint32_t*)&o23;
        ((uint2*)hr)[row * 32 + c] = o;
    } else {
        int idx = ((int)blockIdx.x - IBS - IBR) * blockDim.x + threadIdx.x;
        if (idx >= 4 * 256 * 128) return;
        int l = idx >> 15;
        int rem = idx & 32767;
        int k = rem >> 7, n = rem & 127;
        const float* src = (l & 1) ? (Ws + (size_t)(l >> 1) * 2 * DM * DM)
                                   : (Wr + (size_t)(l >> 1) * 2 * DM * DM);
        g_wt[l][n * 256 + k] = __float2half(src[k * DM + n]);
    }
}

// ---------------------------------------------------------------------------
// Segment sum: 8 edges per warp; 16 lanes cover one 256B row (uint4 = 16B/lane);
// red.global.add.noftz.v4.f16x2 (16B vector RED -> half the L2 atomic ops).
__global__ void k_seg8(const __half* __restrict__ src, __half* __restrict__ dst,
                       const int* __restrict__ es, const int* __restrict__ ed) {
    int t = blockIdx.x * blockDim.x + threadIdx.x;
    int w = t >> 5, lane = t & 31;
    int e0 = w * 8;
    if (e0 >= NED) return;
    int4 sa = *(const int4*)(es + e0);
    int4 sb = *(const int4*)(es + e0 + 4);
    int4 da = *(const int4*)(ed + e0);
    int4 db = *(const int4*)(ed + e0 + 4);
    int sI[8] = {sa.x, sa.y, sa.z, sa.w, sb.x, sb.y, sb.z, sb.w};
    int dI[8] = {da.x, da.y, da.z, da.w, db.x, db.y, db.z, db.w};
    int half = lane >> 4;       // which edge of the pair this lane serves
    int c = lane & 15;          // 16B chunk within the row
    uint4 v[4];
#pragma unroll
    for (int i = 0; i < 4; i++) {
        int s = sI[2 * i + half];
        v[i] = *((const uint4*)(src + (size_t)s * DM) + c);
    }
#pragma unroll
    for (int i = 0; i < 4; i++) {
        int d = dI[2 * i + half];
        __half* p = dst + (size_t)d * DM + c * 8;
        asm volatile("red.global.add.noftz.v4.f16x2 [%0], {%1, %2, %3, %4};"
                     :: "l"(p), "r"(v[i].x), "r"(v[i].y), "r"(v[i].z), "r"(v[i].w)
                     : "memory");
    }
}

// ---------------------------------------------------------------------------
// Paired fp16 tensor-core GEMM, cp.async 2-stage, relu on A fragments.
//   blocks [0, gA):      DA = relu?(XA) @ W[koffA..+128)           (message GEMM)
//   blocks [gA, ...):    DB = relu?(XB) @ W[koffB..+128) + biasB   (state GEMM)
// Single-job launches: jobA-only -> gA = gridDim; jobB-only -> gA = 0.
#define PITCH 72
#define PB    (PITCH * 2)
#define TILEB (128 * PB)
#define STAGEB (2 * TILEB)

__global__ void __launch_bounds__(256, 2) k_gemm_pair(
    __half* __restrict__ DA, const __half* __restrict__ XA,
    const __half* __restrict__ WtA, int nA, int koffA, int reluA, int gA,
    __half* __restrict__ DB, const __half* __restrict__ XB,
    const __half* __restrict__ WtB, const float* __restrict__ biasB,
    int nB, int koffB, int reluB)
{
    extern __shared__ char sm[];
    uint32_t aBase = smem_u32(sm);

    const bool jobB = ((int)blockIdx.x >= gA);
    const __half* X  = jobB ? XB : XA;
    const __half* Wt = jobB ? WtB : WtA;
    const int n      = jobB ? nB : nA;
    const int koff   = jobB ? koffB : koffA;
    const int relu   = jobB ? reluB : reluA;
    const int rowBase = (jobB ? ((int)blockIdx.x - gA) : (int)blockIdx.x) * 128;

    int tid = threadIdx.x;
    int lane = tid & 31, wid = tid >> 5;
    int wm = (wid & 3) * 32;
    int wn = (wid >> 2) * 64;

#pragma unroll
    for (int ch = 0; ch < 2; ch++) {
        uint32_t aX = aBase + ch * STAGEB;
        uint32_t aW = aX + TILEB;
#pragma unroll
        for (int i = 0; i < 4; i++) {
            int f = i * 256 + tid;
            int r = f >> 3, c = f & 7;
            int gr = rowBase + r;
            const __half* gp = X + (size_t)(gr < n ? gr : 0) * DM + ch * 64 + c * 8;
            cpa16(aX + (uint32_t)r * PB + c * 16, gp, (gr < n) ? 16u : 0u);
        }
#pragma unroll
        for (int i = 0; i < 4; i++) {
            int f = i * 256 + tid;
            int r = f >> 3, c = f & 7;
            const __half* gp = Wt + (size_t)r * 256 + koff + ch * 64 + c * 8;
            cpa16(aW + (uint32_t)r * PB + c * 16, gp, 16u);
        }
        asm volatile("cp.async.commit_group;" ::: "memory");
    }

    uint32_t aOff = (uint32_t)(wm + (lane & 15)) * PB + ((lane >> 4) * 8) * 2;
    uint32_t bOff = (uint32_t)(wn + (lane & 7) + ((lane >> 4) & 1) * 8) * PB
                  + (((lane >> 3) & 1) * 8) * 2;

    float acc[2][8][4];
#pragma unroll
    for (int mt = 0; mt < 2; mt++)
#pragma unroll
        for (int nt = 0; nt < 8; nt++)
#pragma unroll
            for (int j = 0; j < 4; j++) acc[mt][nt][j] = 0.f;

    const __half2 z2 = __float2half2_rn(0.f);

#pragma unroll
    for (int ch = 0; ch < 2; ch++) {
        if (ch == 0)
            asm volatile("cp.async.wait_group 1;" ::: "memory");
        else
            asm volatile("cp.async.wait_group 0;" ::: "memory");
        __syncthreads();
        uint32_t aX = aBase + ch * STAGEB;
        uint32_t aW = aX + TILEB;
#pragma unroll
        for (int ks = 0; ks < 4; ks++) {
            uint32_t aF[2][4];
            ldsm4(aF[0], aX + aOff + ks * 32);
            ldsm4(aF[1], aX + aOff + ks * 32 + 16 * PB);
            if (relu) {
#pragma unroll
                for (int mt = 0; mt < 2; mt++)
#pragma unroll
                    for (int j = 0; j < 4; j++) {
                        __half2 h = __hmax2(*(__half2*)&aF[mt][j], z2);
                        aF[mt][j] = *(uint32_t*)&h;
                    }
            }
            uint32_t bF[4][4];
#pragma unroll
            for (int q = 0; q < 4; q++)
                ldsm4(bF[q], aW + bOff + ks * 32 + q * 16 * PB);
#pragma unroll
            for (int mt = 0; mt < 2; mt++)
#pragma unroll
                for (int q = 0; q < 4; q++) {
                    mma16816(acc[mt][q * 2 + 0], aF[mt], bF[q][0], bF[q][1]);
                    mma16816(acc[mt][q * 2 + 1], aF[mt], bF[q][2], bF[q][3]);
                }
        }
    }

    int r0 = (lane >> 2);
    int c0 = (lane & 3) * 2;
    __half* D = jobB ? DB : DA;
#pragma unroll
    for (int mt = 0; mt < 2; mt++) {
#pragma unroll
        for (int nt = 0; nt < 8; nt++) {
            int col = wn + nt * 8 + c0;
            float2 b2 = make_float2(0.f, 0.f);
            if (jobB) b2 = *(const float2*)&biasB[col];
            int rowA = rowBase + wm + mt * 16 + r0;
            int rowB = rowA + 8;
            if (rowA < n)
                *(__half2*)&D[(size_t)rowA * DM + col] =
                    __floats2half2_rn(acc[mt][nt][0] + b2.x, acc[mt][nt][1] + b2.y);
            if (rowB < n)
                *(__half2*)&D[(size_t)rowB * DM + col] =
                    __floats2half2_rn(acc[mt][nt][2] + b2.x, acc[mt][nt][3] + b2.y);
        }
    }
}

// ---------------------------------------------------------------------------
// Pool: fp16 states, relu on load, fp32 accumulation.
__global__ void k_pool(const __half* __restrict__ hs, const __half* __restrict__ hr,
                       float* __restrict__ out) {
    int kind = blockIdx.z;
    int b = blockIdx.y;
    int lane = threadIdx.x & 31;
    int g = threadIdx.x >> 5;
    int col2 = blockIdx.x * 32 + lane;
    const __half* h = kind ? hr : hs;
    int np = kind ? NR_PER : NS_PER;
    float inv = kind ? (1.f / NR_PER) : (1.f / NS_PER);
    size_t base2 = (size_t)b * np * 64;
    const __half2* h2 = (const __half2*)h;
    float sx = 0.f, sy = 0.f;
    for (int i = g; i < np; i += 8) {
        float2 f = __half22float2(h2[base2 + (size_t)i * 64 + col2]);
        sx += fmaxf(f.x, 0.f);
        sy += fmaxf(f.y, 0.f);
    }
    __shared__ float red[8][64];
    red[g][lane * 2]     = sx;
    red[g][lane * 2 + 1] = sy;
    __syncthreads();
    if (g == 0) {
        float tx = 0.f, ty = 0.f;
#pragma unroll
        for (int j = 0; j < 8; j++) { tx += red[j][lane * 2]; ty += red[j][lane * 2 + 1]; }
        int col = col2 * 2;
        out[b * 256 + kind * 128 + col]     = tx * inv;
        out[b * 256 + kind * 128 + col + 1] = ty * inv;
    }
}

// ---------------------------------------------------------------------------
extern "C" void kernel_launch(void* const* d_in, const int* in_sizes, int n_in,
                              void* d_out, int out_size) {
    const int*   species_indices = (const int*)  d_in[0];
    const int*   is_external     = (const int*)  d_in[1];
    const int*   prop_type_ids   = (const int*)  d_in[2];
    const float* prop_params     = (const float*)d_in[3];
    const int*   edge_species    = (const int*)  d_in[4];
    const int*   edge_reaction   = (const int*)  d_in[5];
    const float* species_table   = (const float*)d_in[8];
    const float* external_table  = (const float*)d_in[9];
    const float* type_table      = (const float*)d_in[10];
    const float* W_param         = (const float*)d_in[11];
    const float* b_param         = (const float*)d_in[12];
    const float* Wr              = (const float*)d_in[13];
    const float* br              = (const float*)d_in[14];
    const float* Ws              = (const float*)d_in[15];
    const float* bs              = (const float*)d_in[16];
    float* out = (float*)d_out;

    __half *hsA, *hsB, *hrA, *hrB, *y, *z, *wt;
    cudaGetSymbolAddress((void**)&hsA, g_hsA);
    cudaGetSymbolAddress((void**)&hsB, g_hsB);
    cudaGetSymbolAddress((void**)&hrA, g_hrA);
    cudaGetSymbolAddress((void**)&hrB, g_hrB);
    cudaGetSymbolAddress((void**)&y, g_y);
    cudaGetSymbolAddress((void**)&z, g_z);
    cudaGetSymbolAddress((void**)&wt, g_wt);

    // Side stream + events, created once (first call is the uncaptured
    // correctness run); reused under capture. Work per call is identical.
    static cudaStream_t s1 = nullptr;
    static cudaEvent_t evA, evD, evSeg0, evH, evSeg1, evK;
    if (!s1) {
        cudaStreamCreateWithFlags(&s1, cudaStreamNonBlocking);
        cudaEventCreateWithFlags(&evA,    cudaEventDisableTiming);
        cudaEventCreateWithFlags(&evD,    cudaEventDisableTiming);
        cudaEventCreateWithFlags(&evSeg0, cudaEventDisableTiming);
        cudaEventCreateWithFlags(&evH,    cudaEventDisableTiming);
        cudaEventCreateWithFlags(&evSeg1, cudaEventDisableTiming);
        cudaEventCreateWithFlags(&evK,    cudaEventDisableTiming);
    }

    const int GEMM_SMEM = 2 * STAGEB;
    cudaFuncSetAttribute(k_gemm_pair, cudaFuncAttributeMaxDynamicSharedMemorySize, GEMM_SMEM);

    const int segBlocks = (NED / 8 * 32) / 256;
    const int gS = (NSP + 127) / 128, gR = (NRX + 127) / 128;
    const size_t WSZ = (size_t)128 * 256;
    const __half* Wr0 = wt + 0 * WSZ;
    const __half* Ws0 = wt + 1 * WSZ;
    const __half* Wr1 = wt + 2 * WSZ;
    const __half* Ws1 = wt + 3 * WSZ;

    k_init<<<IBS + IBR + 512, 256>>>(species_indices, is_external, species_table,
                                     external_table, prop_type_ids, prop_params,
                                     type_table, W_param, b_param, Wr, Ws, hsA, hrA);

    // L1: pair  A: y = hsA@Wr2   |  B: hrB = hsA... (hrA@Wr1 + br)
    k_gemm_pair<<<gS + gR, 256, GEMM_SMEM>>>(
        y,   hsA, Wr0, NSP, 128, 0, gS,
        hrB, hrA, Wr0, br,  NRX, 0, 0);
    cudaEventRecord(evA, 0);

    // s1: D: hsB = hsA@Ws1 + bs   (independent of seg0)
    cudaStreamWaitEvent(s1, evA, 0);
    k_gemm_pair<<<gS, 256, GEMM_SMEM, s1>>>(
        nullptr, nullptr, nullptr, 0, 0, 0, 0,
        hsB, hsA, Ws0, bs, NSP, 0, 0);
    cudaEventRecord(evD, s1);

    // seg0: hrB += seg(y)
    k_seg8<<<segBlocks, 256>>>(y, hrB, edge_species, edge_reaction);
    cudaEventRecord(evSeg0, 0);

    // s1: H: hrA = relu(hrB)@Wr1' + br'
    cudaStreamWaitEvent(s1, evSeg0, 0);
    k_gemm_pair<<<gR, 256, GEMM_SMEM, s1>>>(
        nullptr, nullptr, nullptr, 0, 0, 0, 0,
        hrA, hrB, Wr1, br + DM, NRX, 0, 1);
    cudaEventRecord(evH, s1);

    // E: z = relu(hrB)@Ws2
    k_gemm_pair<<<gR, 256, GEMM_SMEM>>>(
        z, hrB, Ws0, NRX, 128, 1, gR,
        nullptr, nullptr, nullptr, nullptr, 0, 0, 0);

    // seg1: hsB += seg(z)   (needs D)
    cudaStreamWaitEvent(0, evD, 0);
    k_seg8<<<segBlocks, 256>>>(z, hsB, edge_reaction, edge_species);
    cudaEventRecord(evSeg1, 0);

    // s1: K: hsA = relu(hsB)@Ws1' + bs'
    cudaStreamWaitEvent(s1, evSeg1, 0);
    k_gemm_pair<<<gS, 256, GEMM_SMEM, s1>>>(
        nullptr, nullptr, nullptr, 0, 0, 0, 0,
        hsA, hsB, Ws1, bs + DM, NSP, 0, 1);
    cudaEventRecord(evK, s1);

    // G: y = relu(hsB)@Wr2'
    k_gemm_pair<<<gS, 256, GEMM_SMEM>>>(
        y, hsB, Wr1, NSP, 128, 1, gS,
        nullptr, nullptr, nullptr, nullptr, 0, 0, 0);

    // seg2: hrA += seg(y)   (needs H)
    cudaStreamWaitEvent(0, evH, 0);
    k_seg8<<<segBlocks, 256>>>(y, hrA, edge_species, edge_reaction);

    // J: z = relu(hrA)@Ws2'
    k_gemm_pair<<<gR, 256, GEMM_SMEM>>>(
        z, hrA, Ws1, NRX, 128, 1, gR,
        nullptr, nullptr, nullptr, nullptr, 0, 0, 0);

    // seg3: hsA += seg(z)   (needs K)
    cudaStreamWaitEvent(0, evK, 0);
    k_seg8<<<segBlocks, 256>>>(z, hsA, edge_reaction, edge_species);

    k_pool<<<dim3(2, BGR, 2), 256>>>(hsA, hrA, out);
}

// round 13
// speedup vs baseline: 1.1985x; 1.1985x over previous
#include <cuda_runtime.h>
#include <cuda_fp16.h>
#include <cstdint>

#define NSP 100000
#define NRX 200000
#define NED 1000000
#define DM  128
#define BGR 50
#define NS_PER 2000
#define NR_PER 4000

// State / message buffers — all fp16
__device__ __half g_hsA[NSP * DM];
__device__ __half g_hsB[NSP * DM];
__device__ __half g_hrA[NRX * DM];
__device__ __half g_hrB[NRX * DM];
__device__ __half g_y[NSP * DM];
__device__ __half g_z[NRX * DM];
// Pre-transposed fp16 weights: [which of 4][n=128][k=256]
__device__ __half g_wt[4][128 * 256];

// ---------------------------------------------------------------------------
__device__ __forceinline__ uint32_t smem_u32(const void* p) {
    uint32_t a;
    asm("{ .reg .u64 t; cvta.to.shared.u64 t, %1; cvt.u32.u64 %0, t; }" : "=r"(a) : "l"(p));
    return a;
}
__device__ __forceinline__ void ldsm4(uint32_t r[4], uint32_t addr) {
    asm volatile("ldmatrix.sync.aligned.m8n8.x4.shared.b16 {%0,%1,%2,%3}, [%4];"
                 : "=r"(r[0]), "=r"(r[1]), "=r"(r[2]), "=r"(r[3]) : "r"(addr));
}
__device__ __forceinline__ void mma16816(float c[4], const uint32_t a[4],
                                         uint32_t b0, uint32_t b1) {
    asm volatile(
        "mma.sync.aligned.m16n8k16.row.col.f32.f16.f16.f32 "
        "{%0,%1,%2,%3}, {%4,%5,%6,%7}, {%8,%9}, {%0,%1,%2,%3};"
        : "+f"(c[0]), "+f"(c[1]), "+f"(c[2]), "+f"(c[3])
        : "r"(a[0]), "r"(a[1]), "r"(a[2]), "r"(a[3]), "r"(b0), "r"(b1));
}
__device__ __forceinline__ void cpa16(uint32_t smem, const void* gmem, uint32_t bytes) {
    asm volatile("cp.async.ca.shared.global [%0], [%1], 16, %2;"
                 :: "r"(smem), "l"(gmem), "r"(bytes) : "memory");
}

// ---------------------------------------------------------------------------
// Fused init + weight prep:
//   blocks [0, IBS)            : h_s init
//   blocks [IBS, IBS+IBR)      : h_r init
//   blocks [IBS+IBR, +512)     : W transpose/convert
#define IBS ((NSP * 32 + 255) / 256)
#define IBR ((NRX * 32 + 255) / 256)
__global__ void k_init(const int* __restrict__ sidx, const int* __restrict__ ext,
                       const float* __restrict__ st, const float* __restrict__ et,
                       const int* __restrict__ tids, const float* __restrict__ params,
                       const float* __restrict__ tt, const float* __restrict__ Wp,
                       const float* __restrict__ bp,
                       const float* __restrict__ Wr, const float* __restrict__ Ws,
                       __half* __restrict__ hs, __half* __restrict__ hr) {
    if ((int)blockIdx.x < IBS) {
        int t = blockIdx.x * blockDim.x + threadIdx.x;
        int row = t >> 5, c = t & 31;
        if (row >= NSP) return;
        int si = sidx[row], ei = ext[row];
        float4 a = ((const float4*)st)[si * 32 + c];
        float4 b = ((const float4*)et)[ei * 32 + c];
        __half2 o01 = __floats2half2_rn(a.x + b.x, a.y + b.y);
        __half2 o23 = __floats2half2_rn(a.z + b.z, a.w + b.w);
        uint2 o;
        o.x = *(uint32_t*)&o01; o.y = *(uint32_t*)&o23;
        ((uint2*)hs)[row * 32 + c] = o;
    } else if ((int)blockIdx.x < IBS + IBR) {
        int t = ((int)blockIdx.x - IBS) * blockDim.x + threadIdx.x;
        int row = t >> 5, c = t & 31;
        if (row >= NRX) return;
        int ti = tids[row];
        float4 acc = ((const float4*)tt)[ti * 32 + c];
        float4 bb  = ((const float4*)bp)[c];
        acc.x += bb.x; acc.y += bb.y; acc.z += bb.z; acc.w += bb.w;
#pragma unroll
        for (int k = 0; k < 8; k++) {
            float p = params[row * 8 + k];
            float4 w = ((const float4*)Wp)[k * 32 + c];
            acc.x += p * w.x; acc.y += p * w.y; acc.z += p * w.z; acc.w += p * w.w;
        }
        __half2 o01 = __floats2half2_rn(acc.x, acc.y);
        __half2 o23 = __floats2half2_rn(acc.z, acc.w);
        uint2 o;
        o.x = *(uint32_t*)&o01; o.y = *(uint32_t*)&o23;
        ((uint2*)hr)[row * 32 + c] = o;
    } else {
        int idx = ((int)blockIdx.x - IBS - IBR) * blockDim.x + threadIdx.x;
        if (idx >= 4 * 256 * 128) return;
        int l = idx >> 15;
        int rem = idx & 32767;
        int k = rem >> 7, n = rem & 127;
        const float* src = (l & 1) ? (Ws + (size_t)(l >> 1) * 2 * DM * DM)
                                   : (Wr + (size_t)(l >> 1) * 2 * DM * DM);
        g_wt[l][n * 256 + k] = __float2half(src[k * DM + n]);
    }
}

// ---------------------------------------------------------------------------
// Segment sum, 8 edges per warp, fp16 rows, v2.f16x2 vector RED (R11-proven).
__global__ void k_seg8(const __half* __restrict__ src, __half* __restrict__ dst,
                       const int* __restrict__ es, const int* __restrict__ ed) {
    int t = blockIdx.x * blockDim.x + threadIdx.x;
    int w = t >> 5, lane = t & 31;
    int e0 = w * 8;
    if (e0 >= NED) return;
    int4 sa = *(const int4*)(es + e0);
    int4 sb = *(const int4*)(es + e0 + 4);
    int4 da = *(const int4*)(ed + e0);
    int4 db = *(const int4*)(ed + e0 + 4);
    int sI[8] = {sa.x, sa.y, sa.z, sa.w, sb.x, sb.y, sb.z, sb.w};
    int dI[8] = {da.x, da.y, da.z, da.w, db.x, db.y, db.z, db.w};
    uint2 v[8];
#pragma unroll
    for (int i = 0; i < 8; i++)
        v[i] = ((const uint2*)(src + (size_t)sI[i] * DM))[lane];
#pragma unroll
    for (int i = 0; i < 8; i++) {
        __half* p = dst + (size_t)dI[i] * DM + lane * 4;
        asm volatile("red.global.add.noftz.v2.f16x2 [%0], {%1, %2};"
                     :: "l"(p), "r"(v[i].x), "r"(v[i].y) : "memory");
    }
}

// ---------------------------------------------------------------------------
// Persistent paired fp16 tensor-core GEMM.
// Grid = 296 CTAs (2/SM). CTAs are split between two jobs proportionally to
// their tile counts. Each CTA loads its job's full W tile (128n x 128k, 34KB)
// into smem ONCE, then loops over row-tiles with double-buffered cp.async X.
//   job A: DA = relu?(XA) @ W[koffA..+128)           (message GEMM)
//   job B: DB = relu?(XB) @ W[koffB..+128) + biasB   (state GEMM)
#define PITCH2 136                 // halfs per smem row (272B, odd multiple of 16B)
#define PB2    (PITCH2 * 2)
#define TILE2  (128 * PB2)         // 34816 B per 128x128 fp16 tile
#define GEMM_GRID 296

__global__ void __launch_bounds__(256, 2) k_gemm_pp(
    __half* __restrict__ DA, const __half* __restrict__ XA,
    const __half* __restrict__ WtA, int nA, int koffA, int reluA,
    __half* __restrict__ DB, const __half* __restrict__ XB,
    const __half* __restrict__ WtB, const float* __restrict__ biasB,
    int nB, int koffB, int reluB)
{
    extern __shared__ char sm[];
    uint32_t aW  = smem_u32(sm);
    uint32_t aX0 = aW + TILE2;
    uint32_t aX1 = aX0 + TILE2;

    int G = gridDim.x;
    int tA = (nA + 127) >> 7, tB = (nB + 127) >> 7;
    int cA = (int)(((long long)G * tA) / (tA + tB));
    if (tA > 0 && cA == 0) cA = 1;
    if (tB > 0 && cA == G) cA = G - 1;

    const bool jobB = ((int)blockIdx.x >= cA);
    const __half* X  = jobB ? XB : XA;
    const __half* Wt = jobB ? WtB : WtA;
    const int n      = jobB ? nB : nA;
    const int koff   = jobB ? koffB : koffA;
    const int relu   = jobB ? reluB : reluA;
    const int nT     = jobB ? tB : tA;
    const int tile0  = jobB ? ((int)blockIdx.x - cA) : (int)blockIdx.x;
    const int stride = jobB ? (G - cA) : cA;
    __half* D = jobB ? DB : DA;

    int tid = threadIdx.x;
    int lane = tid & 31, wid = tid >> 5;
    int wm = (wid & 3) * 32;
    int wn = (wid >> 2) * 64;

    // ---- load W tile once (group) ----
#pragma unroll
    for (int i = 0; i < 8; i++) {
        int f = i * 256 + tid;
        int r = f >> 4, c = f & 15;
        cpa16(aW + (uint32_t)r * PB2 + c * 16,
              Wt + (size_t)r * 256 + koff + c * 8, 16u);
    }
    asm volatile("cp.async.commit_group;" ::: "memory");

    if (tile0 >= nT) {   // idle CTA: still must not leave cp.async dangling
        asm volatile("cp.async.wait_group 0;" ::: "memory");
        return;
    }

    // ---- prologue: X tile0 into buf0 ----
    {
        int rb = tile0 * 128;
#pragma unroll
        for (int i = 0; i < 8; i++) {
            int f = i * 256 + tid;
            int r = f >> 4, c = f & 15;
            int gr = rb + r;
            const __half* gp = X + (size_t)(gr < n ? gr : 0) * DM + c * 8;
            cpa16(aX0 + (uint32_t)r * PB2 + c * 16, gp, (gr < n) ? 16u : 0u);
        }
        asm volatile("cp.async.commit_group;" ::: "memory");
    }

    uint32_t aOff = (uint32_t)(wm + (lane & 15)) * PB2 + ((lane >> 4) * 8) * 2;
    uint32_t bOff = (uint32_t)(wn + (lane & 7) + ((lane >> 4) & 1) * 8) * PB2
                  + (((lane >> 3) & 1) * 8) * 2;
    const __half2 z2 = __float2half2_rn(0.f);

    int t = tile0, buf = 0;
    while (t < nT) {
        int tn = t + stride;
        // issue next X into the other buffer, then wait for current
        if (tn < nT) {
            uint32_t aXn = buf ? aX0 : aX1;
            int rb = tn * 128;
#pragma unroll
            for (int i = 0; i < 8; i++) {
                int f = i * 256 + tid;
                int r = f >> 4, c = f & 15;
                int gr = rb + r;
                const __half* gp = X + (size_t)(gr < n ? gr : 0) * DM + c * 8;
                cpa16(aXn + (uint32_t)r * PB2 + c * 16, gp, (gr < n) ? 16u : 0u);
            }
            asm volatile("cp.async.commit_group;" ::: "memory");
            asm volatile("cp.async.wait_group 1;" ::: "memory");
        } else {
            asm volatile("cp.async.wait_group 0;" ::: "memory");
        }
        __syncthreads();

        uint32_t aX = buf ? aX1 : aX0;
        float acc[2][8][4];
#pragma unroll
        for (int mt = 0; mt < 2; mt++)
#pragma unroll
            for (int nt = 0; nt < 8; nt++)
#pragma unroll
                for (int j = 0; j < 4; j++) acc[mt][nt][j] = 0.f;

#pragma unroll
        for (int ks = 0; ks < 8; ks++) {
            uint32_t aF[2][4];
            ldsm4(aF[0], aX + aOff + ks * 32);
            ldsm4(aF[1], aX + aOff + ks * 32 + 16 * PB2);
            if (relu) {
#pragma unroll
                for (int mt = 0; mt < 2; mt++)
#pragma unroll
                    for (int j = 0; j < 4; j++) {
                        __half2 h = __hmax2(*(__half2*)&aF[mt][j], z2);
                        aF[mt][j] = *(uint32_t*)&h;
                    }
            }
            uint32_t bF[4][4];
#pragma unroll
            for (int q = 0; q < 4; q++)
                ldsm4(bF[q], aW + bOff + ks * 32 + q * 16 * PB2);
#pragma unroll
            for (int mt = 0; mt < 2; mt++)
#pragma unroll
                for (int q = 0; q < 4; q++) {
                    mma16816(acc[mt][q * 2 + 0], aF[mt], bF[q][0], bF[q][1]);
                    mma16816(acc[mt][q * 2 + 1], aF[mt], bF[q][2], bF[q][3]);
                }
        }

        // epilogue: fp16 out; jobB adds bias
        int r0 = (lane >> 2);
        int c0 = (lane & 3) * 2;
        int rowBase = t * 128;
#pragma unroll
        for (int mt = 0; mt < 2; mt++) {
#pragma unroll
            for (int nt = 0; nt < 8; nt++) {
                int col = wn + nt * 8 + c0;
                float2 b2 = make_float2(0.f, 0.f);
                if (jobB) b2 = *(const float2*)&biasB[col];
                int rowA = rowBase + wm + mt * 16 + r0;
                int rowB = rowA + 8;
                if (rowA < n)
                    *(__half2*)&D[(size_t)rowA * DM + col] =
                        __floats2half2_rn(acc[mt][nt][0] + b2.x, acc[mt][nt][1] + b2.y);
                if (rowB < n)
                    *(__half2*)&D[(size_t)rowB * DM + col] =
                        __floats2half2_rn(acc[mt][nt][2] + b2.x, acc[mt][nt][3] + b2.y);
            }
        }
        __syncthreads();   // all reads of aX done before it is refilled
        t = tn;
        buf ^= 1;
    }
}

// ---------------------------------------------------------------------------
// Pool: fp16 states, relu on load, fp32 accumulation.
__global__ void k_pool(const __half* __restrict__ hs, const __half* __restrict__ hr,
                       float* __restrict__ out) {
    int kind = blockIdx.z;
    int b = blockIdx.y;
    int lane = threadIdx.x & 31;
    int g = threadIdx.x >> 5;
    int col2 = blockIdx.x * 32 + lane;
    const __half* h = kind ? hr : hs;
    int np = kind ? NR_PER : NS_PER;
    float inv = kind ? (1.f / NR_PER) : (1.f / NS_PER);
    size_t base2 = (size_t)b * np * 64;
    const __half2* h2 = (const __half2*)h;
    float sx = 0.f, sy = 0.f;
    for (int i = g; i < np; i += 8) {
        float2 f = __half22float2(h2[base2 + (size_t)i * 64 + col2]);
        sx += fmaxf(f.x, 0.f);
        sy += fmaxf(f.y, 0.f);
    }
    __shared__ float red[8][64];
    red[g][lane * 2]     = sx;
    red[g][lane * 2 + 1] = sy;
    __syncthreads();
    if (g == 0) {
        float tx = 0.f, ty = 0.f;
#pragma unroll
        for (int j = 0; j < 8; j++) { tx += red[j][lane * 2]; ty += red[j][lane * 2 + 1]; }
        int col = col2 * 2;
        out[b * 256 + kind * 128 + col]     = tx * inv;
        out[b * 256 + kind * 128 + col + 1] = ty * inv;
    }
}

// ---------------------------------------------------------------------------
extern "C" void kernel_launch(void* const* d_in, const int* in_sizes, int n_in,
                              void* d_out, int out_size) {
    const int*   species_indices = (const int*)  d_in[0];
    const int*   is_external     = (const int*)  d_in[1];
    const int*   prop_type_ids   = (const int*)  d_in[2];
    const float* prop_params     = (const float*)d_in[3];
    const int*   edge_species    = (const int*)  d_in[4];
    const int*   edge_reaction   = (const int*)  d_in[5];
    const float* species_table   = (const float*)d_in[8];
    const float* external_table  = (const float*)d_in[9];
    const float* type_table      = (const float*)d_in[10];
    const float* W_param         = (const float*)d_in[11];
    const float* b_param         = (const float*)d_in[12];
    const float* Wr              = (const float*)d_in[13];
    const float* br              = (const float*)d_in[14];
    const float* Ws              = (const float*)d_in[15];
    const float* bs              = (const float*)d_in[16];
    float* out = (float*)d_out;

    __half *hsA, *hsB, *hrA, *hrB, *y, *z, *wt;
    cudaGetSymbolAddress((void**)&hsA, g_hsA);
    cudaGetSymbolAddress((void**)&hsB, g_hsB);
    cudaGetSymbolAddress((void**)&hrA, g_hrA);
    cudaGetSymbolAddress((void**)&hrB, g_hrB);
    cudaGetSymbolAddress((void**)&y, g_y);
    cudaGetSymbolAddress((void**)&z, g_z);
    cudaGetSymbolAddress((void**)&wt, g_wt);

    const int GEMM_SMEM = 3 * TILE2;   // 104448 B
    cudaFuncSetAttribute(k_gemm_pp, cudaFuncAttributeMaxDynamicSharedMemorySize, GEMM_SMEM);

    k_init<<<IBS + IBR + 512, 256>>>(species_indices, is_external, species_table,
                                     external_table, prop_type_ids, prop_params,
                                     type_table, W_param, b_param, Wr, Ws, hsA, hrA);

    const int segBlocks = (NED / 8 * 32) / 256;   // 15625
    const size_t WSZ = (size_t)128 * 256;
    const __half* Wr0 = wt + 0 * WSZ;
    const __half* Ws0 = wt + 1 * WSZ;
    const __half* Wr1 = wt + 2 * WSZ;
    const __half* Ws1 = wt + 3 * WSZ;

    // ---- layer 0 (inputs raw) ----
    k_gemm_pp<<<GEMM_GRID, 256, GEMM_SMEM>>>(
        y,   hsA, Wr0, NSP, 128, 0,
        hrB, hrA, Wr0, br,  NRX, 0, 0);
    k_seg8<<<segBlocks, 256>>>(y, hrB, edge_species, edge_reaction);
    k_gemm_pp<<<GEMM_GRID, 256, GEMM_SMEM>>>(
        z,   hrB, Ws0, NRX, 128, 1,
        hsB, hsA, Ws0, bs,  NSP, 0, 0);
    k_seg8<<<segBlocks, 256>>>(z, hsB, edge_reaction, edge_species);

    // ---- layer 1 (inputs need relu) ----
    k_gemm_pp<<<GEMM_GRID, 256, GEMM_SMEM>>>(
        y,   hsB, Wr1, NSP, 128, 1,
        hrA, hrB, Wr1, br + DM, NRX, 0, 1);
    k_seg8<<<segBlocks, 256>>>(y, hrA, edge_species, edge_reaction);
    k_gemm_pp<<<GEMM_GRID, 256, GEMM_SMEM>>>(
        z,   hrA, Ws1, NRX, 128, 1,
        hsA, hsB, Ws1, bs + DM, NSP, 0, 1);
    k_seg8<<<segBlocks, 256>>>(z, hsA, edge_reaction, edge_species);

    k_pool<<<dim3(2, BGR, 2), 256>>>(hsA, hrA, out);
}

// round 14
// speedup vs baseline: 1.2554x; 1.0475x over previous
#include <cuda_runtime.h>
#include <cuda_fp16.h>
#include <cstdint>

#define NSP 100000
#define NRX 200000
#define NED 1000000
#define DM  128
#define BGR 50
#define NS_PER 2000
#define NR_PER 4000

// State / message buffers — all fp16
__device__ __half g_hsA[NSP * DM];
__device__ __half g_hsB[NSP * DM];
__device__ __half g_hrA[NRX * DM];
__device__ __half g_hrB[NRX * DM];
__device__ __half g_y[NSP * DM];
__device__ __half g_z[NRX * DM];
// Pre-transposed fp16 weights: [which of 4][n=128][k=256]
__device__ __half g_wt[4][128 * 256];

// ---------------------------------------------------------------------------
__device__ __forceinline__ uint32_t smem_u32(const void* p) {
    uint32_t a;
    asm("{ .reg .u64 t; cvta.to.shared.u64 t, %1; cvt.u32.u64 %0, t; }" : "=r"(a) : "l"(p));
    return a;
}
__device__ __forceinline__ void ldsm4(uint32_t r[4], uint32_t addr) {
    asm volatile("ldmatrix.sync.aligned.m8n8.x4.shared.b16 {%0,%1,%2,%3}, [%4];"
                 : "=r"(r[0]), "=r"(r[1]), "=r"(r[2]), "=r"(r[3]) : "r"(addr));
}
__device__ __forceinline__ void mma16816(float c[4], const uint32_t a[4],
                                         uint32_t b0, uint32_t b1) {
    asm volatile(
        "mma.sync.aligned.m16n8k16.row.col.f32.f16.f16.f32 "
        "{%0,%1,%2,%3}, {%4,%5,%6,%7}, {%8,%9}, {%0,%1,%2,%3};"
        : "+f"(c[0]), "+f"(c[1]), "+f"(c[2]), "+f"(c[3])
        : "r"(a[0]), "r"(a[1]), "r"(a[2]), "r"(a[3]), "r"(b0), "r"(b1));
}
__device__ __forceinline__ void cpa16(uint32_t smem, const void* gmem, uint32_t bytes) {
    asm volatile("cp.async.ca.shared.global [%0], [%1], 16, %2;"
                 :: "r"(smem), "l"(gmem), "r"(bytes) : "memory");
}

// ---------------------------------------------------------------------------
// Fused init + weight prep (unchanged from R13).
#define IBS ((NSP * 32 + 255) / 256)
#define IBR ((NRX * 32 + 255) / 256)
__global__ void k_init(const int* __restrict__ sidx, const int* __restrict__ ext,
                       const float* __restrict__ st, const float* __restrict__ et,
                       const int* __restrict__ tids, const float* __restrict__ params,
                       const float* __restrict__ tt, const float* __restrict__ Wp,
                       const float* __restrict__ bp,
                       const float* __restrict__ Wr, const float* __restrict__ Ws,
                       __half* __restrict__ hs, __half* __restrict__ hr) {
    if ((int)blockIdx.x < IBS) {
        int t = blockIdx.x * blockDim.x + threadIdx.x;
        int row = t >> 5, c = t & 31;
        if (row >= NSP) return;
        int si = sidx[row], ei = ext[row];
        float4 a = ((const float4*)st)[si * 32 + c];
        float4 b = ((const float4*)et)[ei * 32 + c];
        __half2 o01 = __floats2half2_rn(a.x + b.x, a.y + b.y);
        __half2 o23 = __floats2half2_rn(a.z + b.z, a.w + b.w);
        uint2 o;
        o.x = *(uint32_t*)&o01; o.y = *(uint32_t*)&o23;
        ((uint2*)hs)[row * 32 + c] = o;
    } else if ((int)blockIdx.x < IBS + IBR) {
        int t = ((int)blockIdx.x - IBS) * blockDim.x + threadIdx.x;
        int row = t >> 5, c = t & 31;
        if (row >= NRX) return;
        int ti = tids[row];
        float4 acc = ((const float4*)tt)[ti * 32 + c];
        float4 bb  = ((const float4*)bp)[c];
        acc.x += bb.x; acc.y += bb.y; acc.z += bb.z; acc.w += bb.w;
#pragma unroll
        for (int k = 0; k < 8; k++) {
            float p = params[row * 8 + k];
            float4 w = ((const float4*)Wp)[k * 32 + c];
            acc.x += p * w.x; acc.y += p * w.y; acc.z += p * w.z; acc.w += p * w.w;
        }
        __half2 o01 = __floats2half2_rn(acc.x, acc.y);
        __half2 o23 = __floats2half2_rn(acc.z, acc.w);
        uint2 o;
        o.x = *(uint32_t*)&o01; o.y = *(uint32_t*)&o23;
        ((uint2*)hr)[row * 32 + c] = o;
    } else {
        int idx = ((int)blockIdx.x - IBS - IBR) * blockDim.x + threadIdx.x;
        if (idx >= 4 * 256 * 128) return;
        int l = idx >> 15;
        int rem = idx & 32767;
        int k = rem >> 7, n = rem & 127;
        const float* src = (l & 1) ? (Ws + (size_t)(l >> 1) * 2 * DM * DM)
                                   : (Wr + (size_t)(l >> 1) * 2 * DM * DM);
        g_wt[l][n * 256 + k] = __float2half(src[k * DM + n]);
    }
}

// ---------------------------------------------------------------------------
// Segment sum, 8 edges per warp, fp16 rows, v2.f16x2 vector RED (R11-proven).
__global__ void k_seg8(const __half* __restrict__ src, __half* __restrict__ dst,
                       const int* __restrict__ es, const int* __restrict__ ed) {
    int t = blockIdx.x * blockDim.x + threadIdx.x;
    int w = t >> 5, lane = t & 31;
    int e0 = w * 8;
    if (e0 >= NED) return;
    int4 sa = *(const int4*)(es + e0);
    int4 sb = *(const int4*)(es + e0 + 4);
    int4 da = *(const int4*)(ed + e0);
    int4 db = *(const int4*)(ed + e0 + 4);
    int sI[8] = {sa.x, sa.y, sa.z, sa.w, sb.x, sb.y, sb.z, sb.w};
    int dI[8] = {da.x, da.y, da.z, da.w, db.x, db.y, db.z, db.w};
    uint2 v[8];
#pragma unroll
    for (int i = 0; i < 8; i++)
        v[i] = ((const uint2*)(src + (size_t)sI[i] * DM))[lane];
#pragma unroll
    for (int i = 0; i < 8; i++) {
        __half* p = dst + (size_t)dI[i] * DM + lane * 4;
        asm volatile("red.global.add.noftz.v2.f16x2 [%0], {%1, %2};"
                     :: "l"(p), "r"(v[i].x), "r"(v[i].y) : "memory");
    }
}

// ---------------------------------------------------------------------------
// Persistent paired GEMM, B (weight) fragments hoisted into registers.
// 512 threads (16 warps), warp tile 32x32 over a 128x128 CTA tile.
// Per CTA: load W tile to smem once, ldsm B frags (64 regs) once, then loop
// row-tiles with double-buffered cp.async X. Inner loop = A-ldsm + MMA only.
#define PITCH2 136                 // halfs per smem row (272B, 17x16B -> conflict-free)
#define PB2    (PITCH2 * 2)
#define TILE2  (128 * PB2)         // 34816 B
#define GEMM_GRID 148

__global__ void __launch_bounds__(512, 1) k_gemm_pp(
    __half* __restrict__ DA, const __half* __restrict__ XA,
    const __half* __restrict__ WtA, int nA, int koffA, int reluA,
    __half* __restrict__ DB, const __half* __restrict__ XB,
    const __half* __restrict__ WtB, const float* __restrict__ biasB,
    int nB, int koffB, int reluB)
{
    extern __shared__ char sm[];
    uint32_t aW  = smem_u32(sm);
    uint32_t aX0 = aW + TILE2;
    uint32_t aX1 = aX0 + TILE2;

    int G = gridDim.x;
    int tA = (nA + 127) >> 7, tB = (nB + 127) >> 7;
    int cA = (int)(((long long)G * tA) / (tA + tB));
    if (tA > 0 && cA == 0) cA = 1;
    if (tB > 0 && cA == G) cA = G - 1;

    const bool jobB = ((int)blockIdx.x >= cA);
    const __half* X  = jobB ? XB : XA;
    const __half* Wt = jobB ? WtB : WtA;
    const int n      = jobB ? nB : nA;
    const int koff   = jobB ? koffB : koffA;
    const int relu   = jobB ? reluB : reluA;
    const int nT     = jobB ? tB : tA;
    const int tile0  = jobB ? ((int)blockIdx.x - cA) : (int)blockIdx.x;
    const int stride = jobB ? (G - cA) : cA;
    __half* D = jobB ? DB : DA;

    int tid = threadIdx.x;
    int lane = tid & 31, wid = tid >> 5;
    int wm = (wid & 3) * 32;          // 4 m-groups of 32 rows
    int wn = (wid >> 2) * 32;         // 4 n-groups of 32 cols

    // ---- W tile -> smem (one-time) ----
#pragma unroll
    for (int i = 0; i < 4; i++) {
        int f = i * 512 + tid;
        int r = f >> 4, c = f & 15;
        cpa16(aW + (uint32_t)r * PB2 + c * 16,
              Wt + (size_t)r * 256 + koff + c * 8, 16u);
    }
    asm volatile("cp.async.commit_group;" ::: "memory");

    bool active = (tile0 < nT);

    // ---- X tile0 -> buf0 (overlaps W wait) ----
    if (active) {
        int rb = tile0 * 128;
#pragma unroll
        for (int i = 0; i < 4; i++) {
            int f = i * 512 + tid;
            int r = f >> 4, c = f & 15;
            int gr = rb + r;
            const __half* gp = X + (size_t)(gr < n ? gr : 0) * DM + c * 8;
            cpa16(aX0 + (uint32_t)r * PB2 + c * 16, gp, (gr < n) ? 16u : 0u);
        }
    }
    asm volatile("cp.async.commit_group;" ::: "memory");
    asm volatile("cp.async.wait_group 1;" ::: "memory");   // W done
    __syncthreads();

    // ---- hoist B fragments: 8 ks x (2 x ldsm.x4) = 64 regs ----
    uint32_t bOff = (uint32_t)(wn + (lane & 7) + ((lane >> 4) & 1) * 8) * PB2
                  + (((lane >> 3) & 1) * 8) * 2;
    uint32_t bF[8][8];
#pragma unroll
    for (int ks = 0; ks < 8; ks++) {
#pragma unroll
        for (int q = 0; q < 2; q++)
            ldsm4(&bF[ks][q * 4], aW + bOff + ks * 32 + q * 16 * PB2);
    }

    if (!active) {
        asm volatile("cp.async.wait_group 0;" ::: "memory");
        return;
    }

    uint32_t aOff = (uint32_t)(wm + (lane & 15)) * PB2 + ((lane >> 4) * 8) * 2;
    const __half2 z2 = __float2half2_rn(0.f);

    int t = tile0, buf = 0;
    while (t < nT) {
        int tn = t + stride;
        if (tn < nT) {
            uint32_t aXn = buf ? aX0 : aX1;
            int rb = tn * 128;
#pragma unroll
            for (int i = 0; i < 4; i++) {
                int f = i * 512 + tid;
                int r = f >> 4, c = f & 15;
                int gr = rb + r;
                const __half* gp = X + (size_t)(gr < n ? gr : 0) * DM + c * 8;
                cpa16(aXn + (uint32_t)r * PB2 + c * 16, gp, (gr < n) ? 16u : 0u);
            }
            asm volatile("cp.async.commit_group;" ::: "memory");
            asm volatile("cp.async.wait_group 1;" ::: "memory");
        } else {
            asm volatile("cp.async.wait_group 0;" ::: "memory");
        }
        __syncthreads();

        uint32_t aX = buf ? aX1 : aX0;
        float acc[2][4][4];
#pragma unroll
        for (int mt = 0; mt < 2; mt++)
#pragma unroll
            for (int nt = 0; nt < 4; nt++)
#pragma unroll
                for (int j = 0; j < 4; j++) acc[mt][nt][j] = 0.f;

#pragma unroll
        for (int ks = 0; ks < 8; ks++) {
            uint32_t aF[2][4];
            ldsm4(aF[0], aX + aOff + ks * 32);
            ldsm4(aF[1], aX + aOff + ks * 32 + 16 * PB2);
            if (relu) {
#pragma unroll
                for (int mt = 0; mt < 2; mt++)
#pragma unroll
                    for (int j = 0; j < 4; j++) {
                        __half2 h = __hmax2(*(__half2*)&aF[mt][j], z2);
                        aF[mt][j] = *(uint32_t*)&h;
                    }
            }
#pragma unroll
            for (int mt = 0; mt < 2; mt++) {
#pragma unroll
                for (int q = 0; q < 2; q++) {
                    mma16816(acc[mt][q * 2 + 0], aF[mt], bF[ks][q * 4 + 0], bF[ks][q * 4 + 1]);
                    mma16816(acc[mt][q * 2 + 1], aF[mt], bF[ks][q * 4 + 2], bF[ks][q * 4 + 3]);
                }
            }
        }

        // epilogue: fp16 out; jobB adds bias
        int r0 = (lane >> 2);
        int c0 = (lane & 3) * 2;
        int rowBase = t * 128;
#pragma unroll
        for (int mt = 0; mt < 2; mt++) {
#pragma unroll
            for (int nt = 0; nt < 4; nt++) {
                int col = wn + nt * 8 + c0;
                float2 b2 = make_float2(0.f, 0.f);
                if (jobB) b2 = *(const float2*)&biasB[col];
                int rowA = rowBase + wm + mt * 16 + r0;
                int rowB = rowA + 8;
                if (rowA < n)
                    *(__half2*)&D[(size_t)rowA * DM + col] =
                        __floats2half2_rn(acc[mt][nt][0] + b2.x, acc[mt][nt][1] + b2.y);
                if (rowB < n)
                    *(__half2*)&D[(size_t)rowB * DM + col] =
                        __floats2half2_rn(acc[mt][nt][2] + b2.x, acc[mt][nt][3] + b2.y);
            }
        }
        __syncthreads();   // reads of aX done before refill
        t = tn;
        buf ^= 1;
    }
}

// ---------------------------------------------------------------------------
// Pool: fp16 states, relu on load, fp32 accumulation.
__global__ void k_pool(const __half* __restrict__ hs, const __half* __restrict__ hr,
                       float* __restrict__ out) {
    int kind = blockIdx.z;
    int b = blockIdx.y;
    int lane = threadIdx.x & 31;
    int g = threadIdx.x >> 5;
    int col2 = blockIdx.x * 32 + lane;
    const __half* h = kind ? hr : hs;
    int np = kind ? NR_PER : NS_PER;
    float inv = kind ? (1.f / NR_PER) : (1.f / NS_PER);
    size_t base2 = (size_t)b * np * 64;
    const __half2* h2 = (const __half2*)h;
    float sx = 0.f, sy = 0.f;
    for (int i = g; i < np; i += 8) {
        float2 f = __half22float2(h2[base2 + (size_t)i * 64 + col2]);
        sx += fmaxf(f.x, 0.f);
        sy += fmaxf(f.y, 0.f);
    }
    __shared__ float red[8][64];
    red[g][lane * 2]     = sx;
    red[g][lane * 2 + 1] = sy;
    __syncthreads();
    if (g == 0) {
        float tx = 0.f, ty = 0.f;
#pragma unroll
        for (int j = 0; j < 8; j++) { tx += red[j][lane * 2]; ty += red[j][lane * 2 + 1]; }
        int col = col2 * 2;
        out[b * 256 + kind * 128 + col]     = tx * inv;
        out[b * 256 + kind * 128 + col + 1] = ty * inv;
    }
}

// ---------------------------------------------------------------------------
extern "C" void kernel_launch(void* const* d_in, const int* in_sizes, int n_in,
                              void* d_out, int out_size) {
    const int*   species_indices = (const int*)  d_in[0];
    const int*   is_external     = (const int*)  d_in[1];
    const int*   prop_type_ids   = (const int*)  d_in[2];
    const float* prop_params     = (const float*)d_in[3];
    const int*   edge_species    = (const int*)  d_in[4];
    const int*   edge_reaction   = (const int*)  d_in[5];
    const float* species_table   = (const float*)d_in[8];
    const float* external_table  = (const float*)d_in[9];
    const float* type_table      = (const float*)d_in[10];
    const float* W_param         = (const float*)d_in[11];
    const float* b_param         = (const float*)d_in[12];
    const float* Wr              = (const float*)d_in[13];
    const float* br              = (const float*)d_in[14];
    const float* Ws              = (const float*)d_in[15];
    const float* bs              = (const float*)d_in[16];
    float* out = (float*)d_out;

    __half *hsA, *hsB, *hrA, *hrB, *y, *z, *wt;
    cudaGetSymbolAddress((void**)&hsA, g_hsA);
    cudaGetSymbolAddress((void**)&hsB, g_hsB);
    cudaGetSymbolAddress((void**)&hrA, g_hrA);
    cudaGetSymbolAddress((void**)&hrB, g_hrB);
    cudaGetSymbolAddress((void**)&y, g_y);
    cudaGetSymbolAddress((void**)&z, g_z);
    cudaGetSymbolAddress((void**)&wt, g_wt);

    const int GEMM_SMEM = 3 * TILE2;   // 104448 B
    cudaFuncSetAttribute(k_gemm_pp, cudaFuncAttributeMaxDynamicSharedMemorySize, GEMM_SMEM);

    k_init<<<IBS + IBR + 512, 256>>>(species_indices, is_external, species_table,
                                     external_table, prop_type_ids, prop_params,
                                     type_table, W_param, b_param, Wr, Ws, hsA, hrA);

    const int segBlocks = (NED / 8 * 32) / 256;   // 15625
    const size_t WSZ = (size_t)128 * 256;
    const __half* Wr0 = wt + 0 * WSZ;
    const __half* Ws0 = wt + 1 * WSZ;
    const __half* Wr1 = wt + 2 * WSZ;
    const __half* Ws1 = wt + 3 * WSZ;

    // ---- layer 0 (inputs raw) ----
    k_gemm_pp<<<GEMM_GRID, 512, GEMM_SMEM>>>(
        y,   hsA, Wr0, NSP, 128, 0,
        hrB, hrA, Wr0, br,  NRX, 0, 0);
    k_seg8<<<segBlocks, 256>>>(y, hrB, edge_species, edge_reaction);
    k_gemm_pp<<<GEMM_GRID, 512, GEMM_SMEM>>>(
        z,   hrB, Ws0, NRX, 128, 1,
        hsB, hsA, Ws0, bs,  NSP, 0, 0);
    k_seg8<<<segBlocks, 256>>>(z, hsB, edge_reaction, edge_species);

    // ---- layer 1 (inputs need relu) ----
    k_gemm_pp<<<GEMM_GRID, 512, GEMM_SMEM>>>(
        y,   hsB, Wr1, NSP, 128, 1,
        hrA, hrB, Wr1, br + DM, NRX, 0, 1);
    k_seg8<<<segBlocks, 256>>>(y, hrA, edge_species, edge_reaction);
    k_gemm_pp<<<GEMM_GRID, 512, GEMM_SMEM>>>(
        z,   hrA, Ws1, NRX, 128, 1,
        hsA, hsB, Ws1, bs + DM, NRX == 0 ? 0 : NSP, 0, 1);
    k_seg8<<<segBlocks, 256>>>(z, hsA, edge_reaction, edge_species);

    k_pool<<<dim3(2, BGR, 2), 256>>>(hsA, hrA, out);
}